// round 3
// baseline (speedup 1.0000x reference)
#include <cuda_runtime.h>
#include <math.h>
#include <float.h>

#define NPIL 60000
#define PPTS 32
#define SBLK 296   // k_stats block count

// per-block partial moments: [0..9]=sum(feats), [10..64]=upper-tri sum(f f^T)
static __device__ float g_part[SBLK][65];
// per-channel folded params, 16 floats each (4 float4s):
// v0 = Wc (x,y,z,w merged + BN-scaled)
// v1 = {a*W4, a*W5, a*W6, a*W7}   (mean coeffs x,y,z + center coeff x)
// v2 = {a*W8, a*W9, b, 0}         (center coeffs y,z + bias)
// v3 = pad
static __device__ float g_params[64 * 16];
// per-pillar mean + center: [2i]={mx,my,mz,-}, [2i+1]={cx,cy,cz,-}
static __device__ float4 g_pm[NPIL * 2];

__global__ void __launch_bounds__(256) k_stats(const float4* __restrict__ pts,
                                               const int* __restrict__ nvs,
                                               const int4* __restrict__ coords) {
    __shared__ float sred[8 * 65];
    const int lane = threadIdx.x & 31;
    const int warp = threadIdx.x >> 5;
    const int gw = blockIdx.x * 8 + warp;
    const int nw = SBLK * 8;

    float acc[65];
#pragma unroll
    for (int k = 0; k < 65; k++) acc[k] = 0.0f;

    int i = gw;                      // gw < 2368 <= NPIL always
    float4 q = pts[i * PPTS + lane];
    int nv = nvs[i];
    int4 c = coords[i];

    for (;;) {
        const int inext = i + nw;
        const bool more = inext < NPIL;
        float4 qn; int nvn = 0; int4 cn;
        if (more) {                  // prefetch next pillar (hide DRAM latency)
            qn = pts[inext * PPTS + lane];
            nvn = nvs[inext];
            cn = coords[inext];
        }

        // sum of xyz over ALL 32 points (reference sums unmasked, divides by nv)
        float sx = q.x, sy = q.y, sz = q.z;
#pragma unroll
        for (int s = 16; s > 0; s >>= 1) {
            sx += __shfl_xor_sync(0xffffffffu, sx, s);
            sy += __shfl_xor_sync(0xffffffffu, sy, s);
            sz += __shfl_xor_sync(0xffffffffu, sz, s);
        }
        const float inv = 1.0f / (float)nv;
        const float mx = sx * inv, my = sy * inv, mz = sz * inv;
        const float cx = (float)c.w * 0.2f + 0.1f;
        const float cy = (float)c.z * 0.2f - 39.9f;
        const float cz = (float)c.y * 4.0f - 1.0f;
        if (lane == 0) {
            g_pm[2 * i]     = make_float4(mx, my, mz, 0.0f);
            g_pm[2 * i + 1] = make_float4(cx, cy, cz, 0.0f);
        }
        const float valid = (lane < nv) ? 1.0f : 0.0f;
        float f[10];
        f[0] = q.x * valid;        f[1] = q.y * valid;        f[2] = q.z * valid;
        f[3] = q.w * valid;
        f[4] = (q.x - mx) * valid; f[5] = (q.y - my) * valid; f[6] = (q.z - mz) * valid;
        f[7] = (q.x - cx) * valid; f[8] = (q.y - cy) * valid; f[9] = (q.z - cz) * valid;
#pragma unroll
        for (int k = 0; k < 10; k++) acc[k] += f[k];
        int idx = 10;
#pragma unroll
        for (int a = 0; a < 10; a++)
#pragma unroll
            for (int b = a; b < 10; b++)
                acc[idx++] += f[a] * f[b];

        if (!more) break;
        i = inext; q = qn; nv = nvn; c = cn;
    }

    // warp reduce, stage per-warp, block reduce -> per-block partial (no atomics)
#pragma unroll
    for (int k = 0; k < 65; k++) {
        float v = acc[k];
#pragma unroll
        for (int s = 16; s > 0; s >>= 1) v += __shfl_xor_sync(0xffffffffu, v, s);
        if (lane == 0) sred[warp * 65 + k] = v;
    }
    __syncthreads();
    const int t = threadIdx.x;
    if (t < 65) {
        float s = 0.0f;
#pragma unroll
        for (int w = 0; w < 8; w++) s += sred[w * 65 + t];
        g_part[blockIdx.x][t] = s;
    }
}

__global__ void k_bn(const float* __restrict__ W, const float* __restrict__ gamma,
                     const float* __restrict__ beta) {
    __shared__ float s_acc[65];
    const int t = threadIdx.x;
    if (t < 65) {
        float s = 0.0f;
        for (int b = 0; b < SBLK; b++) s += g_part[b][t];
        s_acc[t] = s;
    }
    __syncthreads();
    if (t >= 64) return;
    const int o = t;
    double w[10];
#pragma unroll
    for (int cc = 0; cc < 10; cc++) w[cc] = (double)W[o * 10 + cc];
    const double NP = (double)NPIL * (double)PPTS;
    double mean = 0.0;
#pragma unroll
    for (int cc = 0; cc < 10; cc++) mean += w[cc] * (double)s_acc[cc];
    mean /= NP;
    double e2 = 0.0;
    int idx = 10;
#pragma unroll
    for (int a = 0; a < 10; a++)
#pragma unroll
        for (int b = a; b < 10; b++) {
            double m = (double)s_acc[idx++];
            e2 += w[a] * w[b] * m * ((a == b) ? 1.0 : 2.0);
        }
    e2 /= NP;
    const double var = e2 - mean * mean;
    const double aa = (double)gamma[o] / sqrt(var + 1e-3);
    const double bb = (double)beta[o] - mean * aa;
    float* p = g_params + o * 16;
    p[0]  = (float)(aa * (w[0] + w[4] + w[7]));
    p[1]  = (float)(aa * (w[1] + w[5] + w[8]));
    p[2]  = (float)(aa * (w[2] + w[6] + w[9]));
    p[3]  = (float)(aa * w[3]);
    p[4]  = (float)(aa * w[4]);
    p[5]  = (float)(aa * w[5]);
    p[6]  = (float)(aa * w[6]);
    p[7]  = (float)(aa * w[7]);
    p[8]  = (float)(aa * w[8]);
    p[9]  = (float)(aa * w[9]);
    p[10] = (float)bb;
    p[11] = 0.0f;
    p[12] = 0.0f; p[13] = 0.0f; p[14] = 0.0f; p[15] = 0.0f;
}

// Output kernel: warp = pillar (grid-stride). Hot loop: 4-wide unroll,
// 8 independent max accumulators, only Wc (2 float4) resident in regs.
// pb coefficients staged in shared memory (cold path, 4 LDS.128/pillar).
// max_p(pb + d_p) == pb + max_p(d_p).
__global__ void __launch_bounds__(256, 4) k_out(const float4* __restrict__ pts,
                                                const int* __restrict__ nvs,
                                                float* __restrict__ out) {
    __shared__ float4 sp[8][32];
    __shared__ float4 s_par[64 * 4];
    const int lane = threadIdx.x & 31;
    const int warp = threadIdx.x >> 5;

    // stage params into shared (256 threads, 256 float4s)
    s_par[threadIdx.x] = ((const float4*)g_params)[threadIdx.x];
    __syncthreads();

    const float4 wc0 = s_par[lane * 4 + 0];
    const float4 wc1 = s_par[(lane + 32) * 4 + 0];

    const int gw = blockIdx.x * 8 + warp;
    const int nw = gridDim.x * 8;

    int i = gw;
    if (i >= NPIL) return;
    float4 q = pts[i * PPTS + lane];
    int nv = nvs[i];

    for (;;) {
        sp[warp][lane] = q;
        __syncwarp();

        const int inext = i + nw;
        const bool more = inext < NPIL;
        float4 qn; int nvn = 0;
        if (more) {
            qn = pts[inext * PPTS + lane];
            nvn = nvs[inext];
        }

        // pillar bias (off the max loop's critical path)
        const float4 pm = g_pm[2 * i];
        const float4 pc = g_pm[2 * i + 1];
        const float4 c0m = s_par[lane * 4 + 1];
        const float4 c0t = s_par[lane * 4 + 2];
        const float4 c1m = s_par[(lane + 32) * 4 + 1];
        const float4 c1t = s_par[(lane + 32) * 4 + 2];
        const float pb0 = c0t.z - (pm.x * c0m.x + pm.y * c0m.y + pm.z * c0m.z)
                                - (pc.x * c0m.w + pc.y * c0t.x + pc.z * c0t.y);
        const float pb1 = c1t.z - (pm.x * c1m.x + pm.y * c1m.y + pm.z * c1m.z)
                                - (pc.x * c1m.w + pc.y * c1t.x + pc.z * c1t.y);

        const float4* s4 = sp[warp];
        float m0 = -FLT_MAX, m1 = -FLT_MAX, m2 = -FLT_MAX, m3 = -FLT_MAX;
        float n0 = -FLT_MAX, n1 = -FLT_MAX, n2 = -FLT_MAX, n3 = -FLT_MAX;
        int p = 0;
        for (; p + 4 <= nv; p += 4) {
            const float4 r0 = s4[p];
            const float4 r1 = s4[p + 1];
            const float4 r2 = s4[p + 2];
            const float4 r3 = s4[p + 3];
            m0 = fmaxf(m0, fmaf(r0.x, wc0.x, fmaf(r0.y, wc0.y, fmaf(r0.z, wc0.z, r0.w * wc0.w))));
            m1 = fmaxf(m1, fmaf(r1.x, wc0.x, fmaf(r1.y, wc0.y, fmaf(r1.z, wc0.z, r1.w * wc0.w))));
            m2 = fmaxf(m2, fmaf(r2.x, wc0.x, fmaf(r2.y, wc0.y, fmaf(r2.z, wc0.z, r2.w * wc0.w))));
            m3 = fmaxf(m3, fmaf(r3.x, wc0.x, fmaf(r3.y, wc0.y, fmaf(r3.z, wc0.z, r3.w * wc0.w))));
            n0 = fmaxf(n0, fmaf(r0.x, wc1.x, fmaf(r0.y, wc1.y, fmaf(r0.z, wc1.z, r0.w * wc1.w))));
            n1 = fmaxf(n1, fmaf(r1.x, wc1.x, fmaf(r1.y, wc1.y, fmaf(r1.z, wc1.z, r1.w * wc1.w))));
            n2 = fmaxf(n2, fmaf(r2.x, wc1.x, fmaf(r2.y, wc1.y, fmaf(r2.z, wc1.z, r2.w * wc1.w))));
            n3 = fmaxf(n3, fmaf(r3.x, wc1.x, fmaf(r3.y, wc1.y, fmaf(r3.z, wc1.z, r3.w * wc1.w))));
        }
        for (; p < nv; p++) {
            const float4 r0 = s4[p];
            m0 = fmaxf(m0, fmaf(r0.x, wc0.x, fmaf(r0.y, wc0.y, fmaf(r0.z, wc0.z, r0.w * wc0.w))));
            n0 = fmaxf(n0, fmaf(r0.x, wc1.x, fmaf(r0.y, wc1.y, fmaf(r0.z, wc1.z, r0.w * wc1.w))));
        }
        __syncwarp();   // tile reads done before next iteration's store

        float r0 = pb0 + fmaxf(fmaxf(m0, m1), fmaxf(m2, m3));
        float r1 = pb1 + fmaxf(fmaxf(n0, n1), fmaxf(n2, n3));
        if (nv < PPTS) {   // masked points contribute exactly b pre-ReLU
            r0 = fmaxf(r0, c0t.z);
            r1 = fmaxf(r1, c1t.z);
        }
        out[i * 64 + lane]      = fmaxf(r0, 0.0f);
        out[i * 64 + 32 + lane] = fmaxf(r1, 0.0f);

        if (!more) break;
        i = inext; q = qn; nv = nvn;
    }
}

extern "C" void kernel_launch(void* const* d_in, const int* in_sizes, int n_in,
                              void* d_out, int out_size) {
    const float4* feats  = (const float4*)d_in[0];
    const int*    nvs    = (const int*)d_in[1];
    const int4*   coords = (const int4*)d_in[2];
    const float*  W      = (const float*)d_in[3];
    const float*  gamma  = (const float*)d_in[4];
    const float*  beta   = (const float*)d_in[5];
    float* out = (float*)d_out;

    k_stats<<<SBLK, 256>>>(feats, nvs, coords);
    k_bn<<<1, 128>>>(W, gamma, beta);
    k_out<<<1184, 256>>>(feats, nvs, out);
}